// round 16
// baseline (speedup 1.0000x reference)
#include <cuda_runtime.h>
#include <math.h>

#define NPTS 4096
#define BATCH 4
#define KNN 20
#define EPSBN 1e-5f
#define SLOPE 0.2f
#define SPLIT1 8
#define SPLIT2 8
#define FINF __int_as_float(0x7f800000)

// packed f32x2 ops (sm_103a)
#define FMA2(acc, qa, cb) asm("fma.rn.f32x2 %0, %1, %2, %0;" : "+l"(acc) : "l"(qa), "l"(cb))
#define ADD2(dst, a, b)   asm("add.rn.f32x2 %0, %1, %2;" : "=l"(dst) : "l"(a), "l"(b))
#define UNPK2(lo, hi, v)  asm("mov.b64 {%0,%1}, %2;" : "=r"(lo), "=r"(hi) : "l"(v))

// ------------------------- scratch (no allocation allowed) -------------------------
__device__ float S_x1p[BATCH*NPTS*64];   // point-major x1 [b][n][64]
__device__ float S_x2p[BATCH*NPTS*64];   // point-major x2
__device__ float S_xx1[BATCH*NPTS];      // ||x1||^2 per point
__device__ int   S_idx2[BATCH*NPTS*KNN];
__device__ uint2 S_k1[BATCH*NPTS*SPLIT1*KNN];   // partial (floatbits, idx) lists knn1
__device__ uint2 S_k2[BATCH*NPTS*SPLIT2*KNN];   // partial (floatbits, idx) lists knn2
__device__ float S_A1[128],  S_B1[128],  S_t1[64];
__device__ float S_A2[4096], S_B2[4096], S_t2[64];
__device__ float S_A5[16384], S_t5[128];
__device__ float S_A6t[65536], S_t6[256];
__device__ unsigned S_gmaxenc[512];

__device__ __forceinline__ float lrelu(float v){ return v >= 0.f ? v : SLOPE*v; }
__device__ __forceinline__ unsigned encf(float f){
    unsigned u = __float_as_uint(f);
    return (u & 0x80000000u) ? ~u : (u | 0x80000000u);
}
__device__ __forceinline__ float decf(unsigned u){
    return __uint_as_float((u & 0x80000000u) ? (u & 0x7FFFFFFFu) : ~u);
}

// Register-resident sorted top-K insert, float distance + parallel index.
// Strict '<' + ascending candidate scan == lax.top_k lower-index-wins tie-break.
__device__ __forceinline__ void dinsf(float (&bd)[KNN], int (&bi)[KNN], float d, int idx){
    if (d < bd[KNN-1]){
        #pragma unroll
        for (int j = KNN-1; j >= 1; j--){
            bool p  = d < bd[j];
            bool pm = d < bd[j-1];
            float nd = pm ? bd[j-1] : d;
            int   ni = pm ? bi[j-1] : idx;
            bd[j] = p ? nd : bd[j];
            bi[j] = p ? ni : bi[j];
        }
        if (d < bd[0]){ bd[0] = d; bi[0] = idx; }
    }
}

__device__ __forceinline__ void flushbuf(const uint2* mybuf, int& cnt,
                                         float (&bd)[KNN], int (&bi)[KNN], float& worst){
    int cmax = (int)__reduce_max_sync(0xffffffffu, (unsigned)cnt);
    for (int i = 0; i < cmax; i++){
        if (i < cnt){
            uint2 e = mybuf[i];
            dinsf(bd, bi, __uint_as_float(e.x), (int)e.y);
        }
    }
    cnt = 0;
    worst = bd[KNN-1];
}

// ------------------------- prep kernels (2 launches; layer1 lands in profiled slot 4) --------
__global__ void prep_a(const float* __restrict__ W6, const float* __restrict__ g6,
                       const float* __restrict__ v6){
    for (int i = blockIdx.x*blockDim.x + threadIdx.x; i < 65536; i += gridDim.x*blockDim.x){
        int d = i >> 8, o = i & 255;
        float s = g6[o] / sqrtf(v6[o] + EPSBN);
        S_A6t[i] = s * W6[o*256 + d];
    }
}

__global__ void prep_bc(
    const float* __restrict__ W1, const float* __restrict__ g1, const float* __restrict__ b1,
    const float* __restrict__ m1, const float* __restrict__ v1,
    const float* __restrict__ W2, const float* __restrict__ g2, const float* __restrict__ b2,
    const float* __restrict__ m2, const float* __restrict__ v2,
    const float* __restrict__ W5, const float* __restrict__ g5, const float* __restrict__ b5,
    const float* __restrict__ m5, const float* __restrict__ v5,
    const float* __restrict__ g6, const float* __restrict__ b6,
    const float* __restrict__ m6, const float* __restrict__ v6)
{
    for (int i = blockIdx.x*blockDim.x + threadIdx.x; i < 16384; i += gridDim.x*blockDim.x){
        {
            int o = i >> 7;
            float s = g5[o] / sqrtf(v5[o] + EPSBN);
            S_A5[i] = s * W5[i];
        }
        if (i < 4096){
            int o = i >> 6, d = i & 63;
            float s = g2[o] / sqrtf(v2[o] + EPSBN);
            S_A2[i] = s * W2[o*128 + d];
            S_B2[i] = s * (W2[o*128 + 64 + d] - W2[o*128 + d]);
        }
        if (i < 128){
            int o = i >> 1, c = i & 1;
            float s = g1[o] / sqrtf(v1[o] + EPSBN);
            S_A1[i] = s * W1[o*4 + c];
            S_B1[i] = s * (W1[o*4 + 2 + c] - W1[o*4 + c]);
        }
        if (i < 64){
            float s1 = g1[i] / sqrtf(v1[i] + EPSBN);
            S_t1[i] = b1[i] - m1[i]*s1;
            float s2 = g2[i] / sqrtf(v2[i] + EPSBN);
            S_t2[i] = b2[i] - m2[i]*s2;
        }
        if (i < 128){
            float s = g5[i] / sqrtf(v5[i] + EPSBN);
            S_t5[i] = b5[i] - m5[i]*s;
        }
        if (i < 256){
            float s = g6[i] / sqrtf(v6[i] + EPSBN);
            S_t6[i] = b6[i] - m6[i]*s;
        }
        if (i < 512) S_gmaxenc[i] = 0u;
    }
}

// ------------------------- knn1 partial: 2-D points, SPLIT1=8 (grid-limit fix) ---------------
__global__ void __launch_bounds__(128) knn1_part(const float* __restrict__ x){
    int b = blockIdx.z, s = blockIdx.y;
    int n = blockIdx.x*128 + threadIdx.x;
    const float* xb = x + b*2*NPTS;
    float qx = xb[n], qy = xb[NPTS + n];

    __shared__ float2 sxy[NPTS/SPLIT1];    // 4KB interleaved
    __shared__ uint2  sbuf[128*12];        // 12KB
    int c0 = s*(NPTS/SPLIT1);
    for (int i = threadIdx.x; i < NPTS/SPLIT1; i += 128)
        sxy[i] = make_float2(xb[c0 + i], xb[NPTS + c0 + i]);
    __syncthreads();

    float bd[KNN]; int bi[KNN];
    #pragma unroll
    for (int k = 0; k < KNN; k++){ bd[k] = FINF; bi[k] = 0; }

    #pragma unroll
    for (int m = 0; m < KNN; m++){
        float2 p = sxy[m];
        float dx = qx - p.x, dy = qy - p.y;
        dinsf(bd, bi, fmaf(dx, dx, dy*dy), c0 + m);
    }
    float worst = bd[KNN-1];
    int cnt = 0;
    uint2* mybuf = sbuf + threadIdx.x*12;

    for (int ml = KNN; ml < NPTS/SPLIT1; ml += 4){   // (512-20) = 4*123
        #pragma unroll
        for (int u = 0; u < 4; u++){
            int m = ml + u;
            float2 p = sxy[m];
            float dx = qx - p.x, dy = qy - p.y;
            float d = fmaf(dx, dx, dy*dy);
            if (d < worst){
                mybuf[cnt] = make_uint2(__float_as_uint(d), (unsigned)(c0 + m));
                cnt++;
            }
        }
        if (__any_sync(0xffffffffu, cnt >= 8))
            flushbuf(mybuf, cnt, bd, bi, worst);
    }
    flushbuf(mybuf, cnt, bd, bi, worst);

    uint2* o = S_k1 + ((long)(b*NPTS + n)*SPLIT1 + s)*KNN;
    #pragma unroll
    for (int k = 0; k < KNN; k++) o[k] = make_uint2(__float_as_uint(bd[k]), (unsigned)bi[k]);
}

// ------------------------- layer1: fused merge of knn1 partials + edgeconv 4->64 --------------
__global__ void layer1_kernel(const float* __restrict__ x){
    __shared__ float sA[128], sB[128], sT[64];
    int t = threadIdx.x;
    if (t < 128){ sA[t] = S_A1[t]; sB[t] = S_B1[t]; }
    if (t < 64)  sT[t] = S_t1[t];
    __syncthreads();

    int b = blockIdx.y;
    int n = blockIdx.x*blockDim.x + t;
    int bn = b*NPTS + n;
    const float* xb = x + b*2*NPTS;
    float cx = xb[n], cy = xb[NPTS + n];

    float bd[KNN]; int bi[KNN];
    #pragma unroll
    for (int k = 0; k < KNN; k++){ bd[k] = FINF; bi[k] = 0; }
    const uint2* p = S_k1 + (long)bn*SPLIT1*KNN;
    #pragma unroll 4
    for (int c = 0; c < SPLIT1*KNN; c++){
        uint2 e = p[c];
        dinsf(bd, bi, __uint_as_float(e.x), (int)e.y);
    }

    float nx[KNN], ny[KNN];
    #pragma unroll
    for (int k = 0; k < KNN; k++){
        int m = bi[k];
        nx[k] = xb[m]; ny[k] = xb[NPTS + m];
    }

    float xx = 0.f;
    float* outp = S_x1p + (long)bn*64;
    for (int o = 0; o < 64; o++){
        float w0 = sA[2*o], w1 = sA[2*o+1];
        float base = fmaf(sB[2*o], cx, fmaf(sB[2*o+1], cy, sT[o]));
        float best = -3.4e38f;
        #pragma unroll
        for (int k = 0; k < KNN; k++){
            float v = fmaf(w0, nx[k], fmaf(w1, ny[k], base));
            best = fmaxf(best, lrelu(v));
        }
        outp[o] = best;
        xx = fmaf(best, best, xx);
    }
    S_xx1[bn] = xx;
}

// ------------------------- knn2 partial: 8q x 8c GEMM tile, conflict-free smem (R12) ---------
#define QT 128
#define CT 64
#define NTILES ((NPTS/SPLIT2)/CT)
#define QROW 160
#define CROW 80
#define DROW 68
#define KNN2_SMEM 107264

__global__ void __launch_bounds__(128, 2) knn2_part(){
    extern __shared__ char dynsm[];
    unsigned long long* Qs = (unsigned long long*)(dynsm);
    unsigned long long* Cs = (unsigned long long*)(dynsm + 40960);
    float* Ds   = (float*)(dynsm + 61440);
    float* sxxq = (float*)(dynsm + 96256);
    float* sxxc = (float*)(dynsm + 96768);
    uint2* sbuf = (uint2*)(dynsm + 97024);

    int b = blockIdx.z, s = blockIdx.y;
    int t = threadIdx.x;
    int q0 = blockIdx.x*QT;
    int bn = b*NPTS + q0 + t;

    {
        const unsigned long long* src = (const unsigned long long*)(S_x1p + (long)bn*64);
        int qoff = (t >> 3)*10 + (t & 7);
        #pragma unroll
        for (int kp = 0; kp < 32; kp++) Qs[kp*QROW + qoff] = src[kp];
        sxxq[t] = S_xx1[bn];
    }

    float bd[KNN]; int bi[KNN];
    #pragma unroll
    for (int k = 0; k < KNN; k++){ bd[k] = FINF; bi[k] = 0; }
    float worst = FINF;
    int cnt = 0;
    uint2* mybuf = sbuf + t*10;

    int qg = t >> 3;
    int cg = t & 7;
    int c0 = s*(NPTS/SPLIT2);

    for (int tt = 0; tt < NTILES; tt++){
        int cb = c0 + tt*CT;
        {
            int c = t & 63, h = t >> 6;
            const unsigned long long* csrc =
                (const unsigned long long*)(S_x1p + (long)(b*NPTS + cb + c)*64) + h*16;
            int coff = (c >> 3)*10 + (c & 7);
            #pragma unroll
            for (int j = 0; j < 16; j++) Cs[(h*16 + j)*CROW + coff] = csrc[j];
            if (t < CT) sxxc[t] = S_xx1[b*NPTS + cb + t];
        }
        __syncthreads();

        unsigned long long acc[8][8];
        #pragma unroll
        for (int i = 0; i < 8; i++)
            #pragma unroll
            for (int j = 0; j < 8; j++) acc[i][j] = 0ull;

        #pragma unroll 4
        for (int kp = 0; kp < 32; kp++){
            const ulonglong2* qp = (const ulonglong2*)(Qs + kp*QROW + qg*10);
            const ulonglong2* cp = (const ulonglong2*)(Cs + kp*CROW + cg*10);
            ulonglong2 q01 = qp[0], q23 = qp[1], q45 = qp[2], q67 = qp[3];
            ulonglong2 c01 = cp[0], c23 = cp[1], c45 = cp[2], c67 = cp[3];
            unsigned long long qr[8] = {q01.x, q01.y, q23.x, q23.y, q45.x, q45.y, q67.x, q67.y};
            unsigned long long cr[8] = {c01.x, c01.y, c23.x, c23.y, c45.x, c45.y, c67.x, c67.y};
            #pragma unroll
            for (int i = 0; i < 8; i++)
                #pragma unroll
                for (int j = 0; j < 8; j++)
                    FMA2(acc[i][j], qr[i], cr[j]);
        }

        #pragma unroll
        for (int i = 0; i < 8; i++){
            float xq = sxxq[qg*8 + i];
            float dd[8];
            #pragma unroll
            for (int j = 0; j < 8; j++){
                unsigned lo, hi; UNPK2(lo, hi, acc[i][j]);
                float dot = __uint_as_float(lo) + __uint_as_float(hi);
                dd[j] = fmaf(-2.f, dot, xq + sxxc[cg*8 + j]);
            }
            float* drow = Ds + (qg*8 + i)*DROW + cg*8;
            *(float4*)(drow)     = make_float4(dd[0], dd[1], dd[2], dd[3]);
            *(float4*)(drow + 4) = make_float4(dd[4], dd[5], dd[6], dd[7]);
        }
        __syncthreads();

        const float* row = Ds + t*DROW;
        if (tt == 0){
            #pragma unroll 4
            for (int c = 0; c < CT; c++)
                dinsf(bd, bi, row[c], cb + c);
            worst = bd[KNN-1];
        } else {
            for (int c = 0; c < CT; c += 4){
                float4 r4 = *(const float4*)(row + c);
                float rv[4] = {r4.x, r4.y, r4.z, r4.w};
                #pragma unroll
                for (int u = 0; u < 4; u++){
                    if (rv[u] < worst){
                        mybuf[cnt] = make_uint2(__float_as_uint(rv[u]), (unsigned)(cb + c + u));
                        cnt++;
                    }
                }
                if (__any_sync(0xffffffffu, cnt >= 7))
                    flushbuf(mybuf, cnt, bd, bi, worst);
            }
        }
    }
    flushbuf(mybuf, cnt, bd, bi, worst);

    uint2* o = S_k2 + ((long)bn*SPLIT2 + s)*KNN;
    #pragma unroll
    for (int k = 0; k < KNN; k++) o[k] = make_uint2(__float_as_uint(bd[k]), (unsigned)bi[k]);
}

// ------------------------- merge knn2 partial lists (exact) -------------------------
__global__ void merge2_kernel(){
    int t = blockIdx.x*blockDim.x + threadIdx.x;
    float bd[KNN]; int bi[KNN];
    #pragma unroll
    for (int k = 0; k < KNN; k++){ bd[k] = FINF; bi[k] = 0; }
    const uint2* p = S_k2 + (long)t*SPLIT2*KNN;
    #pragma unroll 4
    for (int c = 0; c < SPLIT2*KNN; c++){
        uint2 e = p[c];
        dinsf(bd, bi, __uint_as_float(e.x), (int)e.y);
    }
    int* o = S_idx2 + t*KNN;
    #pragma unroll
    for (int k = 0; k < KNN; k++) o[k] = bi[k];
}

// ------------------------- layer2: edgeconv 128->64, 2 points/block -------------------------
__global__ void __launch_bounds__(128) layer2_kernel(){
    int t = threadIdx.x;
    int pp = t >> 6;               // point within block
    int ch = t & 63;               // output channel
    int bn = blockIdx.x*2 + pp;
    int b = bn >> 12;

    __shared__ float  ctr[2][64];
    __shared__ float4 nbr[2][KNN*16];

    ctr[pp][ch] = S_x1p[(long)bn*64 + ch];
    for (int k = 0; k < KNN; k++){
        int m = S_idx2[bn*KNN + k];
        ((float*)nbr[pp])[k*64 + ch] = S_x1p[((long)b*NPTS + m)*64 + ch];
    }
    __syncthreads();

    unsigned long long au[32];
    const unsigned long long* ap = (const unsigned long long*)(S_A2 + ch*64);
    #pragma unroll
    for (int i = 0; i < 32; i++) au[i] = ap[i];

    float base = S_t2[ch];
    {
        const float4* bp = (const float4*)(S_B2 + ch*64);
        const float4* cp = (const float4*)ctr[pp];
        #pragma unroll
        for (int i = 0; i < 16; i++){
            float4 w = bp[i], c = cp[i];
            base = fmaf(w.x, c.x, fmaf(w.y, c.y, fmaf(w.z, c.z, fmaf(w.w, c.w, base))));
        }
    }

    float best = -3.4e38f;
    for (int k = 0; k < KNN; k++){
        const ulonglong2* nv = (const ulonglong2*)(nbr[pp] + k*16);
        unsigned long long a0 = 0ull, a1 = 0ull, a2 = 0ull, a3 = 0ull;
        #pragma unroll
        for (int i = 0; i < 16; i += 2){
            ulonglong2 v0 = nv[i];
            ulonglong2 v1 = nv[i+1];
            FMA2(a0, au[2*i],   v0.x);
            FMA2(a1, au[2*i+1], v0.y);
            FMA2(a2, au[2*i+2], v1.x);
            FMA2(a3, au[2*i+3], v1.y);
        }
        unsigned long long t0, t1;
        ADD2(t0, a0, a1);
        ADD2(t1, a2, a3);
        ADD2(t0, t0, t1);
        unsigned lo, hi; UNPK2(lo, hi, t0);
        float sdot = __uint_as_float(lo) + __uint_as_float(hi);
        best = fmaxf(best, lrelu(sdot + base));
    }
    S_x2p[(long)bn*64 + ch] = best;
}

// ------------------------- conv5 (128x128) fused with global max, 32 pts/block ---------------
#define C5PTS 32
__global__ void __launch_bounds__(128) conv5_kernel(){
    int b = blockIdx.y;
    int p0 = blockIdx.x*C5PTS;
    int t = threadIdx.x;

    __shared__ float xc[C5PTS][128];
    #pragma unroll 8
    for (int p = 0; p < C5PTS; p++){
        int bn = b*NPTS + p0 + p;
        xc[p][t] = (t < 64) ? S_x1p[(long)bn*64 + t] : S_x2p[(long)bn*64 + t - 64];
    }
    __syncthreads();

    float4 a[32];
    const float4* ap = (const float4*)(S_A5 + t*128);
    #pragma unroll
    for (int i = 0; i < 32; i++) a[i] = ap[i];
    float tv = S_t5[t];

    float mx = -3.4e38f;
    for (int p = 0; p < C5PTS; p++){
        const float4* cp = (const float4*)xc[p];
        float s0 = 0.f, s1 = 0.f, s2 = 0.f, s3 = 0.f;
        #pragma unroll
        for (int i = 0; i < 32; i += 4){
            float4 v0 = cp[i],   v1 = cp[i+1], v2 = cp[i+2], v3 = cp[i+3];
            s0 = fmaf(a[i].x,   v0.x, fmaf(a[i].y,   v0.y, fmaf(a[i].z,   v0.z, fmaf(a[i].w,   v0.w, s0))));
            s1 = fmaf(a[i+1].x, v1.x, fmaf(a[i+1].y, v1.y, fmaf(a[i+1].z, v1.z, fmaf(a[i+1].w, v1.w, s1))));
            s2 = fmaf(a[i+2].x, v2.x, fmaf(a[i+2].y, v2.y, fmaf(a[i+2].z, v2.z, fmaf(a[i+2].w, v2.w, s2))));
            s3 = fmaf(a[i+3].x, v3.x, fmaf(a[i+3].y, v3.y, fmaf(a[i+3].z, v3.z, fmaf(a[i+3].w, v3.w, s3))));
        }
        mx = fmaxf(mx, lrelu(((s0+s1)+(s2+s3)) + tv));
    }
    atomicMax(&S_gmaxenc[b*128 + t], encf(mx));
}

// ------------------------- conv6 (256x256) tiled SGEMM fused with W9 epilogue -------------------------
__global__ void conv6_kernel(const float* __restrict__ W9, float* __restrict__ out){
    extern __shared__ float dyn[];
    float* At = dyn;            // [256 k][64 o]
    float* Bt = dyn + 16384;    // [64 p][260]
    __shared__ float red[64];

    int tid = threadIdx.x;
    int p0 = blockIdx.x*64;
    int b  = p0 >> 12;

    for (int i = tid; i < 64*256; i += 256){
        int pl = i >> 8, kl = i & 255;
        float v;
        if (kl < 128)       v = decf(S_gmaxenc[b*128 + kl]);
        else if (kl < 192)  v = S_x1p[((long)p0 + pl)*64 + (kl - 128)];
        else                v = S_x2p[((long)p0 + pl)*64 + (kl - 192)];
        Bt[pl*260 + kl] = v;
    }

    int og = tid & 15, pg = tid >> 4;
    int o = og*4, p = pg*4;
    float psum[4] = {0.f, 0.f, 0.f, 0.f};

    for (int ot = 0; ot < 4; ot++){
        __syncthreads();
        for (int i = tid; i < 16384; i += 256){
            int ol = i & 63, kl = i >> 6;
            At[kl*64 + ol] = S_A6t[kl*256 + ot*64 + ol];
        }
        __syncthreads();

        float acc[16];
        #pragma unroll
        for (int i = 0; i < 16; i++) acc[i] = 0.f;

        for (int k4 = 0; k4 < 64; k4++){
            int kb = k4*4;
            float4 a0 = *(const float4*)&At[(kb+0)*64 + o];
            float4 a1 = *(const float4*)&At[(kb+1)*64 + o];
            float4 a2 = *(const float4*)&At[(kb+2)*64 + o];
            float4 a3 = *(const float4*)&At[(kb+3)*64 + o];
            #pragma unroll
            for (int pj = 0; pj < 4; pj++){
                float4 bv = *(const float4*)&Bt[(p+pj)*260 + kb];
                acc[0*4+pj] = fmaf(a0.x, bv.x, fmaf(a1.x, bv.y, fmaf(a2.x, bv.z, fmaf(a3.x, bv.w, acc[0*4+pj]))));
                acc[1*4+pj] = fmaf(a0.y, bv.x, fmaf(a1.y, bv.y, fmaf(a2.y, bv.z, fmaf(a3.y, bv.w, acc[1*4+pj]))));
                acc[2*4+pj] = fmaf(a0.z, bv.x, fmaf(a1.z, bv.y, fmaf(a2.z, bv.z, fmaf(a3.z, bv.w, acc[2*4+pj]))));
                acc[3*4+pj] = fmaf(a0.w, bv.x, fmaf(a1.w, bv.y, fmaf(a2.w, bv.z, fmaf(a3.w, bv.w, acc[3*4+pj]))));
            }
        }

        #pragma unroll
        for (int oi = 0; oi < 4; oi++){
            int oglob = ot*64 + o + oi;
            float tt = S_t6[oglob];
            float w  = W9[oglob];
            #pragma unroll
            for (int pj = 0; pj < 4; pj++){
                float h = lrelu(acc[oi*4+pj] + tt);
                psum[pj] = fmaf(h, w, psum[pj]);
            }
        }
    }

    __syncthreads();
    if (tid < 64) red[tid] = 0.f;
    __syncthreads();
    #pragma unroll
    for (int pj = 0; pj < 4; pj++) atomicAdd(&red[p+pj], psum[pj]);
    __syncthreads();
    if (tid < 64) out[p0 + tid] = red[tid];
}

// ------------------------- launch -------------------------
extern "C" void kernel_launch(void* const* d_in, const int* in_sizes, int n_in,
                              void* d_out, int out_size){
    const float* x  = (const float*)d_in[0];
    const float* W1 = (const float*)d_in[1];
    const float* g1 = (const float*)d_in[2];
    const float* b1 = (const float*)d_in[3];
    const float* m1 = (const float*)d_in[4];
    const float* v1 = (const float*)d_in[5];
    const float* W2 = (const float*)d_in[6];
    const float* g2 = (const float*)d_in[7];
    const float* b2 = (const float*)d_in[8];
    const float* m2 = (const float*)d_in[9];
    const float* v2 = (const float*)d_in[10];
    const float* W5 = (const float*)d_in[11];
    const float* g5 = (const float*)d_in[12];
    const float* b5 = (const float*)d_in[13];
    const float* m5 = (const float*)d_in[14];
    const float* v5 = (const float*)d_in[15];
    const float* W6 = (const float*)d_in[16];
    const float* g6 = (const float*)d_in[17];
    const float* b6 = (const float*)d_in[18];
    const float* m6 = (const float*)d_in[19];
    const float* v6 = (const float*)d_in[20];
    const float* W9 = (const float*)d_in[21];
    float* out = (float*)d_out;

    cudaFuncSetAttribute(conv6_kernel, cudaFuncAttributeMaxDynamicSharedMemorySize, 132096);
    cudaFuncSetAttribute(knn2_part, cudaFuncAttributeMaxDynamicSharedMemorySize, KNN2_SMEM);

    prep_a<<<64, 256>>>(W6, g6, v6);
    prep_bc<<<16, 256>>>(W1, g1, b1, m1, v1, W2, g2, b2, m2, v2,
                         W5, g5, b5, m5, v5, g6, b6, m6, v6);

    knn1_part<<<dim3(32, SPLIT1, BATCH), 128>>>(x);   // 3rd

    dim3 g32(32, 4);
    layer1_kernel<<<g32, 128>>>(x);                   // 4th launch -> profiled next round

    knn2_part<<<dim3(32, SPLIT2, BATCH), 128, KNN2_SMEM>>>();

    merge2_kernel<<<64, 256>>>();

    layer2_kernel<<<BATCH*NPTS/2, 128>>>();

    conv5_kernel<<<dim3(NPTS/C5PTS, BATCH), 128>>>();

    conv6_kernel<<<256, 256, 132096>>>(W9, out);
}

// round 17
// speedup vs baseline: 1.0294x; 1.0294x over previous
#include <cuda_runtime.h>
#include <math.h>

#define NPTS 4096
#define BATCH 4
#define KNN 20
#define EPSBN 1e-5f
#define SLOPE 0.2f
#define SPLIT1 4
#define SPLIT2 8
#define FINF __int_as_float(0x7f800000)

// packed f32x2 ops (sm_103a)
#define FMA2(acc, qa, cb) asm("fma.rn.f32x2 %0, %1, %2, %0;" : "+l"(acc) : "l"(qa), "l"(cb))
#define ADD2(dst, a, b)   asm("add.rn.f32x2 %0, %1, %2;" : "=l"(dst) : "l"(a), "l"(b))
#define UNPK2(lo, hi, v)  asm("mov.b64 {%0,%1}, %2;" : "=r"(lo), "=r"(hi) : "l"(v))

// ------------------------- scratch (no allocation allowed) -------------------------
__device__ float S_x1p[BATCH*NPTS*64];   // point-major x1 [b][n][64]
__device__ float S_x2p[BATCH*NPTS*64];   // point-major x2
__device__ float S_xx1[BATCH*NPTS];      // ||x1||^2 per point
__device__ int   S_idx2[BATCH*NPTS*KNN];
__device__ uint2 S_k1[BATCH*NPTS*SPLIT1*KNN];   // partial (floatbits, idx) lists knn1
__device__ uint2 S_k2[BATCH*NPTS*SPLIT2*KNN];   // partial (floatbits, idx) lists knn2
__device__ float S_A1[128],  S_B1[128],  S_t1[64];
__device__ float S_A2[4096], S_B2[4096], S_t2[64];
__device__ float S_A5[16384], S_t5[128];
__device__ float S_A6t[65536], S_t6[256];
__device__ unsigned S_gmaxenc[512];

__device__ __forceinline__ float lrelu(float v){ return v >= 0.f ? v : SLOPE*v; }
__device__ __forceinline__ unsigned encf(float f){
    unsigned u = __float_as_uint(f);
    return (u & 0x80000000u) ? ~u : (u | 0x80000000u);
}
__device__ __forceinline__ float decf(unsigned u){
    return __uint_as_float((u & 0x80000000u) ? (u & 0x7FFFFFFFu) : ~u);
}

// Register-resident sorted top-K insert, float distance + parallel index.
// Strict '<' + ascending candidate scan == lax.top_k lower-index-wins tie-break.
__device__ __forceinline__ void dinsf(float (&bd)[KNN], int (&bi)[KNN], float d, int idx){
    if (d < bd[KNN-1]){
        #pragma unroll
        for (int j = KNN-1; j >= 1; j--){
            bool p  = d < bd[j];
            bool pm = d < bd[j-1];
            float nd = pm ? bd[j-1] : d;
            int   ni = pm ? bi[j-1] : idx;
            bd[j] = p ? nd : bd[j];
            bi[j] = p ? ni : bi[j];
        }
        if (d < bd[0]){ bd[0] = d; bi[0] = idx; }
    }
}

__device__ __forceinline__ void flushbuf(const uint2* mybuf, int& cnt,
                                         float (&bd)[KNN], int (&bi)[KNN], float& worst){
    int cmax = (int)__reduce_max_sync(0xffffffffu, (unsigned)cnt);
    for (int i = 0; i < cmax; i++){
        if (i < cnt){
            uint2 e = mybuf[i];
            dinsf(bd, bi, __uint_as_float(e.x), (int)e.y);
        }
    }
    cnt = 0;
    worst = bd[KNN-1];
}

// ------------------------- prep kernels -------------------------
__global__ void prep_a(const float* __restrict__ W6, const float* __restrict__ g6,
                       const float* __restrict__ v6){
    for (int i = blockIdx.x*blockDim.x + threadIdx.x; i < 65536; i += gridDim.x*blockDim.x){
        int d = i >> 8, o = i & 255;
        float s = g6[o] / sqrtf(v6[o] + EPSBN);
        S_A6t[i] = s * W6[o*256 + d];
    }
}

__global__ void prep_bc(
    const float* __restrict__ W1, const float* __restrict__ g1, const float* __restrict__ b1,
    const float* __restrict__ m1, const float* __restrict__ v1,
    const float* __restrict__ W2, const float* __restrict__ g2, const float* __restrict__ b2,
    const float* __restrict__ m2, const float* __restrict__ v2,
    const float* __restrict__ W5, const float* __restrict__ g5, const float* __restrict__ b5,
    const float* __restrict__ m5, const float* __restrict__ v5,
    const float* __restrict__ g6, const float* __restrict__ b6,
    const float* __restrict__ m6, const float* __restrict__ v6)
{
    for (int i = blockIdx.x*blockDim.x + threadIdx.x; i < 16384; i += gridDim.x*blockDim.x){
        {
            int o = i >> 7;
            float s = g5[o] / sqrtf(v5[o] + EPSBN);
            S_A5[i] = s * W5[i];
        }
        if (i < 4096){
            int o = i >> 6, d = i & 63;
            float s = g2[o] / sqrtf(v2[o] + EPSBN);
            S_A2[i] = s * W2[o*128 + d];
            S_B2[i] = s * (W2[o*128 + 64 + d] - W2[o*128 + d]);
        }
        if (i < 128){
            int o = i >> 1, c = i & 1;
            float s = g1[o] / sqrtf(v1[o] + EPSBN);
            S_A1[i] = s * W1[o*4 + c];
            S_B1[i] = s * (W1[o*4 + 2 + c] - W1[o*4 + c]);
        }
        if (i < 64){
            float s1 = g1[i] / sqrtf(v1[i] + EPSBN);
            S_t1[i] = b1[i] - m1[i]*s1;
            float s2 = g2[i] / sqrtf(v2[i] + EPSBN);
            S_t2[i] = b2[i] - m2[i]*s2;
        }
        if (i < 128){
            float s = g5[i] / sqrtf(v5[i] + EPSBN);
            S_t5[i] = b5[i] - m5[i]*s;
        }
        if (i < 256){
            float s = g6[i] / sqrtf(v6[i] + EPSBN);
            S_t6[i] = b6[i] - m6[i]*s;
        }
        if (i < 512) S_gmaxenc[i] = 0u;
    }
}

// ------------------------- knn1 partial: 2-D points, SPLIT1=4 -------------------------
__global__ void __launch_bounds__(128) knn1_part(const float* __restrict__ x){
    int b = blockIdx.z, s = blockIdx.y;
    int n = blockIdx.x*128 + threadIdx.x;
    const float* xb = x + b*2*NPTS;
    float qx = xb[n], qy = xb[NPTS + n];

    __shared__ float2 sxy[NPTS/SPLIT1];    // 8KB interleaved
    __shared__ uint2  sbuf[128*12];        // 12KB
    int c0 = s*(NPTS/SPLIT1);
    for (int i = threadIdx.x; i < NPTS/SPLIT1; i += 128)
        sxy[i] = make_float2(xb[c0 + i], xb[NPTS + c0 + i]);
    __syncthreads();

    float bd[KNN]; int bi[KNN];
    #pragma unroll
    for (int k = 0; k < KNN; k++){ bd[k] = FINF; bi[k] = 0; }

    #pragma unroll
    for (int m = 0; m < KNN; m++){
        float2 p = sxy[m];
        float dx = qx - p.x, dy = qy - p.y;
        dinsf(bd, bi, fmaf(dx, dx, dy*dy), c0 + m);
    }
    float worst = bd[KNN-1];
    int cnt = 0;
    uint2* mybuf = sbuf + threadIdx.x*12;

    for (int ml = KNN; ml < NPTS/SPLIT1; ml += 4){
        #pragma unroll
        for (int u = 0; u < 4; u++){
            int m = ml + u;
            float2 p = sxy[m];
            float dx = qx - p.x, dy = qy - p.y;
            float d = fmaf(dx, dx, dy*dy);
            if (d < worst){
                mybuf[cnt] = make_uint2(__float_as_uint(d), (unsigned)(c0 + m));
                cnt++;
            }
        }
        if (__any_sync(0xffffffffu, cnt >= 8))
            flushbuf(mybuf, cnt, bd, bi, worst);
    }
    flushbuf(mybuf, cnt, bd, bi, worst);

    uint2* o = S_k1 + ((long)(b*NPTS + n)*SPLIT1 + s)*KNN;
    #pragma unroll
    for (int k = 0; k < KNN; k++) o[k] = make_uint2(__float_as_uint(bd[k]), (unsigned)bi[k]);
}

// ------------------------- layer1: fused merge of knn1 partials + edgeconv 4->64 --------------
__global__ void layer1_kernel(const float* __restrict__ x){
    __shared__ float sA[128], sB[128], sT[64];
    int t = threadIdx.x;
    if (t < 128){ sA[t] = S_A1[t]; sB[t] = S_B1[t]; }
    if (t < 64)  sT[t] = S_t1[t];
    __syncthreads();

    int b = blockIdx.y;
    int n = blockIdx.x*blockDim.x + t;
    int bn = b*NPTS + n;
    const float* xb = x + b*2*NPTS;
    float cx = xb[n], cy = xb[NPTS + n];

    float bd[KNN]; int bi[KNN];
    #pragma unroll
    for (int k = 0; k < KNN; k++){ bd[k] = FINF; bi[k] = 0; }
    const uint2* p = S_k1 + (long)bn*SPLIT1*KNN;
    #pragma unroll 4
    for (int c = 0; c < SPLIT1*KNN; c++){
        uint2 e = p[c];
        dinsf(bd, bi, __uint_as_float(e.x), (int)e.y);
    }

    float nx[KNN], ny[KNN];
    #pragma unroll
    for (int k = 0; k < KNN; k++){
        int m = bi[k];
        nx[k] = xb[m]; ny[k] = xb[NPTS + m];
    }

    float xx = 0.f;
    float* outp = S_x1p + (long)bn*64;
    for (int o = 0; o < 64; o++){
        float w0 = sA[2*o], w1 = sA[2*o+1];
        float base = fmaf(sB[2*o], cx, fmaf(sB[2*o+1], cy, sT[o]));
        float best = -3.4e38f;
        #pragma unroll
        for (int k = 0; k < KNN; k++){
            float v = fmaf(w0, nx[k], fmaf(w1, ny[k], base));
            best = fmaxf(best, lrelu(v));
        }
        outp[o] = best;
        xx = fmaf(best, best, xx);
    }
    S_xx1[bn] = xx;
}

// ------------------------- knn2 partial: 8q x 8c GEMM tile, conflict-free smem (R12) ---------
#define QT 128
#define CT 64
#define NTILES ((NPTS/SPLIT2)/CT)
#define QROW 160
#define CROW 80
#define DROW 68
#define KNN2_SMEM 107264

__global__ void __launch_bounds__(128, 2) knn2_part(){
    extern __shared__ char dynsm[];
    unsigned long long* Qs = (unsigned long long*)(dynsm);
    unsigned long long* Cs = (unsigned long long*)(dynsm + 40960);
    float* Ds   = (float*)(dynsm + 61440);
    float* sxxq = (float*)(dynsm + 96256);
    float* sxxc = (float*)(dynsm + 96768);
    uint2* sbuf = (uint2*)(dynsm + 97024);

    int b = blockIdx.z, s = blockIdx.y;
    int t = threadIdx.x;
    int q0 = blockIdx.x*QT;
    int bn = b*NPTS + q0 + t;

    {
        const unsigned long long* src = (const unsigned long long*)(S_x1p + (long)bn*64);
        int qoff = (t >> 3)*10 + (t & 7);
        #pragma unroll
        for (int kp = 0; kp < 32; kp++) Qs[kp*QROW + qoff] = src[kp];
        sxxq[t] = S_xx1[bn];
    }

    float bd[KNN]; int bi[KNN];
    #pragma unroll
    for (int k = 0; k < KNN; k++){ bd[k] = FINF; bi[k] = 0; }
    float worst = FINF;
    int cnt = 0;
    uint2* mybuf = sbuf + t*10;

    int qg = t >> 3;
    int cg = t & 7;
    int c0 = s*(NPTS/SPLIT2);

    for (int tt = 0; tt < NTILES; tt++){
        int cb = c0 + tt*CT;
        {
            int c = t & 63, h = t >> 6;
            const unsigned long long* csrc =
                (const unsigned long long*)(S_x1p + (long)(b*NPTS + cb + c)*64) + h*16;
            int coff = (c >> 3)*10 + (c & 7);
            #pragma unroll
            for (int j = 0; j < 16; j++) Cs[(h*16 + j)*CROW + coff] = csrc[j];
            if (t < CT) sxxc[t] = S_xx1[b*NPTS + cb + t];
        }
        __syncthreads();

        unsigned long long acc[8][8];
        #pragma unroll
        for (int i = 0; i < 8; i++)
            #pragma unroll
            for (int j = 0; j < 8; j++) acc[i][j] = 0ull;

        #pragma unroll 4
        for (int kp = 0; kp < 32; kp++){
            const ulonglong2* qp = (const ulonglong2*)(Qs + kp*QROW + qg*10);
            const ulonglong2* cp = (const ulonglong2*)(Cs + kp*CROW + cg*10);
            ulonglong2 q01 = qp[0], q23 = qp[1], q45 = qp[2], q67 = qp[3];
            ulonglong2 c01 = cp[0], c23 = cp[1], c45 = cp[2], c67 = cp[3];
            unsigned long long qr[8] = {q01.x, q01.y, q23.x, q23.y, q45.x, q45.y, q67.x, q67.y};
            unsigned long long cr[8] = {c01.x, c01.y, c23.x, c23.y, c45.x, c45.y, c67.x, c67.y};
            #pragma unroll
            for (int i = 0; i < 8; i++)
                #pragma unroll
                for (int j = 0; j < 8; j++)
                    FMA2(acc[i][j], qr[i], cr[j]);
        }

        #pragma unroll
        for (int i = 0; i < 8; i++){
            float xq = sxxq[qg*8 + i];
            float dd[8];
            #pragma unroll
            for (int j = 0; j < 8; j++){
                unsigned lo, hi; UNPK2(lo, hi, acc[i][j]);
                float dot = __uint_as_float(lo) + __uint_as_float(hi);
                dd[j] = fmaf(-2.f, dot, xq + sxxc[cg*8 + j]);
            }
            float* drow = Ds + (qg*8 + i)*DROW + cg*8;
            *(float4*)(drow)     = make_float4(dd[0], dd[1], dd[2], dd[3]);
            *(float4*)(drow + 4) = make_float4(dd[4], dd[5], dd[6], dd[7]);
        }
        __syncthreads();

        const float* row = Ds + t*DROW;
        if (tt == 0){
            #pragma unroll 4
            for (int c = 0; c < CT; c++)
                dinsf(bd, bi, row[c], cb + c);
            worst = bd[KNN-1];
        } else {
            for (int c = 0; c < CT; c += 4){
                float4 r4 = *(const float4*)(row + c);
                float rv[4] = {r4.x, r4.y, r4.z, r4.w};
                #pragma unroll
                for (int u = 0; u < 4; u++){
                    if (rv[u] < worst){
                        mybuf[cnt] = make_uint2(__float_as_uint(rv[u]), (unsigned)(cb + c + u));
                        cnt++;
                    }
                }
                if (__any_sync(0xffffffffu, cnt >= 7))
                    flushbuf(mybuf, cnt, bd, bi, worst);
            }
        }
    }
    flushbuf(mybuf, cnt, bd, bi, worst);

    uint2* o = S_k2 + ((long)bn*SPLIT2 + s)*KNN;
    #pragma unroll
    for (int k = 0; k < KNN; k++) o[k] = make_uint2(__float_as_uint(bd[k]), (unsigned)bi[k]);
}

// ------------------------- merge knn2 partial lists (exact) -------------------------
__global__ void merge2_kernel(){
    int t = blockIdx.x*blockDim.x + threadIdx.x;
    float bd[KNN]; int bi[KNN];
    #pragma unroll
    for (int k = 0; k < KNN; k++){ bd[k] = FINF; bi[k] = 0; }
    const uint2* p = S_k2 + (long)t*SPLIT2*KNN;
    #pragma unroll 4
    for (int c = 0; c < SPLIT2*KNN; c++){
        uint2 e = p[c];
        dinsf(bd, bi, __uint_as_float(e.x), (int)e.y);
    }
    int* o = S_idx2 + t*KNN;
    #pragma unroll
    for (int k = 0; k < KNN; k++) o[k] = bi[k];
}

// ------------------------- layer2: edgeconv 128->64, 2 points/block -------------------------
__global__ void __launch_bounds__(128) layer2_kernel(){
    int t = threadIdx.x;
    int pp = t >> 6;
    int ch = t & 63;
    int bn = blockIdx.x*2 + pp;
    int b = bn >> 12;

    __shared__ float  ctr[2][64];
    __shared__ float4 nbr[2][KNN*16];

    ctr[pp][ch] = S_x1p[(long)bn*64 + ch];
    for (int k = 0; k < KNN; k++){
        int m = S_idx2[bn*KNN + k];
        ((float*)nbr[pp])[k*64 + ch] = S_x1p[((long)b*NPTS + m)*64 + ch];
    }
    __syncthreads();

    unsigned long long au[32];
    const unsigned long long* ap = (const unsigned long long*)(S_A2 + ch*64);
    #pragma unroll
    for (int i = 0; i < 32; i++) au[i] = ap[i];

    float base = S_t2[ch];
    {
        const float4* bp = (const float4*)(S_B2 + ch*64);
        const float4* cp = (const float4*)ctr[pp];
        #pragma unroll
        for (int i = 0; i < 16; i++){
            float4 w = bp[i], c = cp[i];
            base = fmaf(w.x, c.x, fmaf(w.y, c.y, fmaf(w.z, c.z, fmaf(w.w, c.w, base))));
        }
    }

    float best = -3.4e38f;
    for (int k = 0; k < KNN; k++){
        const ulonglong2* nv = (const ulonglong2*)(nbr[pp] + k*16);
        unsigned long long a0 = 0ull, a1 = 0ull, a2 = 0ull, a3 = 0ull;
        #pragma unroll
        for (int i = 0; i < 16; i += 2){
            ulonglong2 v0 = nv[i];
            ulonglong2 v1 = nv[i+1];
            FMA2(a0, au[2*i],   v0.x);
            FMA2(a1, au[2*i+1], v0.y);
            FMA2(a2, au[2*i+2], v1.x);
            FMA2(a3, au[2*i+3], v1.y);
        }
        unsigned long long t0, t1;
        ADD2(t0, a0, a1);
        ADD2(t1, a2, a3);
        ADD2(t0, t0, t1);
        unsigned lo, hi; UNPK2(lo, hi, t0);
        float sdot = __uint_as_float(lo) + __uint_as_float(hi);
        best = fmaxf(best, lrelu(sdot + base));
    }
    S_x2p[(long)bn*64 + ch] = best;
}

// ------------------------- conv5 (128x128) fused with global max, 32 pts/block ---------------
#define C5PTS 32
__global__ void __launch_bounds__(128) conv5_kernel(){
    int b = blockIdx.y;
    int p0 = blockIdx.x*C5PTS;
    int t = threadIdx.x;

    __shared__ float xc[C5PTS][128];
    #pragma unroll 8
    for (int p = 0; p < C5PTS; p++){
        int bn = b*NPTS + p0 + p;
        xc[p][t] = (t < 64) ? S_x1p[(long)bn*64 + t] : S_x2p[(long)bn*64 + t - 64];
    }
    __syncthreads();

    float4 a[32];
    const float4* ap = (const float4*)(S_A5 + t*128);
    #pragma unroll
    for (int i = 0; i < 32; i++) a[i] = ap[i];
    float tv = S_t5[t];

    float mx = -3.4e38f;
    for (int p = 0; p < C5PTS; p++){
        const float4* cp = (const float4*)xc[p];
        float s0 = 0.f, s1 = 0.f, s2 = 0.f, s3 = 0.f;
        #pragma unroll
        for (int i = 0; i < 32; i += 4){
            float4 v0 = cp[i],   v1 = cp[i+1], v2 = cp[i+2], v3 = cp[i+3];
            s0 = fmaf(a[i].x,   v0.x, fmaf(a[i].y,   v0.y, fmaf(a[i].z,   v0.z, fmaf(a[i].w,   v0.w, s0))));
            s1 = fmaf(a[i+1].x, v1.x, fmaf(a[i+1].y, v1.y, fmaf(a[i+1].z, v1.z, fmaf(a[i+1].w, v1.w, s1))));
            s2 = fmaf(a[i+2].x, v2.x, fmaf(a[i+2].y, v2.y, fmaf(a[i+2].z, v2.z, fmaf(a[i+2].w, v2.w, s2))));
            s3 = fmaf(a[i+3].x, v3.x, fmaf(a[i+3].y, v3.y, fmaf(a[i+3].z, v3.z, fmaf(a[i+3].w, v3.w, s3))));
        }
        mx = fmaxf(mx, lrelu(((s0+s1)+(s2+s3)) + tv));
    }
    atomicMax(&S_gmaxenc[b*128 + t], encf(mx));
}

// ------------------------- conv6: o-tile 32 for 2 blocks/SM (occupancy fix) ------------------
// smem: At [256k][32o] = 32768B | Bt [64p][260] = 66560B | red 256B -> 99584B total
#define C6_SMEM 99584
__global__ void __launch_bounds__(256, 2) conv6_kernel(const float* __restrict__ W9,
                                                       float* __restrict__ out){
    extern __shared__ float dyn[];
    float* At  = dyn;             // [256 k][32 o]
    float* Bt  = dyn + 8192;      // [64 p][260]
    float* red = dyn + 24832;     // [64]

    int tid = threadIdx.x;
    int p0 = blockIdx.x*64;
    int b  = p0 >> 12;

    for (int i = tid; i < 64*256; i += 256){
        int pl = i >> 8, kl = i & 255;
        float v;
        if (kl < 128)       v = decf(S_gmaxenc[b*128 + kl]);
        else if (kl < 192)  v = S_x1p[((long)p0 + pl)*64 + (kl - 128)];
        else                v = S_x2p[((long)p0 + pl)*64 + (kl - 192)];
        Bt[pl*260 + kl] = v;
    }

    int og = tid & 7, pg = tid >> 3;
    int o = og*4, p = pg*2;
    float psum[2] = {0.f, 0.f};

    for (int ot = 0; ot < 8; ot++){
        __syncthreads();
        // load At tile: 256k x 32o = 8192 floats
        for (int i = tid; i < 8192; i += 256){
            int ol = i & 31, kl = i >> 5;
            At[kl*32 + ol] = S_A6t[kl*256 + ot*32 + ol];
        }
        __syncthreads();

        float acc[8];   // [oi 4][pj 2]
        #pragma unroll
        for (int i = 0; i < 8; i++) acc[i] = 0.f;

        for (int k4 = 0; k4 < 64; k4++){
            int kb = k4*4;
            float4 a0 = *(const float4*)&At[(kb+0)*32 + o];
            float4 a1 = *(const float4*)&At[(kb+1)*32 + o];
            float4 a2 = *(const float4*)&At[(kb+2)*32 + o];
            float4 a3 = *(const float4*)&At[(kb+3)*32 + o];
            #pragma unroll
            for (int pj = 0; pj < 2; pj++){
                float4 bv = *(const float4*)&Bt[(p+pj)*260 + kb];
                acc[0*2+pj] = fmaf(a0.x, bv.x, fmaf(a1.x, bv.y, fmaf(a2.x, bv.z, fmaf(a3.x, bv.w, acc[0*2+pj]))));
                acc[1*2+pj] = fmaf(a0.y, bv.x, fmaf(a1.y, bv.y, fmaf(a2.y, bv.z, fmaf(a3.y, bv.w, acc[1*2+pj]))));
                acc[2*2+pj] = fmaf(a0.z, bv.x, fmaf(a1.z, bv.y, fmaf(a2.z, bv.z, fmaf(a3.z, bv.w, acc[2*2+pj]))));
                acc[3*2+pj] = fmaf(a0.w, bv.x, fmaf(a1.w, bv.y, fmaf(a2.w, bv.z, fmaf(a3.w, bv.w, acc[3*2+pj]))));
            }
        }

        #pragma unroll
        for (int oi = 0; oi < 4; oi++){
            int oglob = ot*32 + o + oi;
            float tt = S_t6[oglob];
            float w  = W9[oglob];
            #pragma unroll
            for (int pj = 0; pj < 2; pj++){
                float h = lrelu(acc[oi*2+pj] + tt);
                psum[pj] = fmaf(h, w, psum[pj]);
            }
        }
    }

    __syncthreads();
    if (tid < 64) red[tid] = 0.f;
    __syncthreads();
    #pragma unroll
    for (int pj = 0; pj < 2; pj++) atomicAdd(&red[p+pj], psum[pj]);
    __syncthreads();
    if (tid < 64) out[p0 + tid] = red[tid];
}

// ------------------------- launch -------------------------
extern "C" void kernel_launch(void* const* d_in, const int* in_sizes, int n_in,
                              void* d_out, int out_size){
    const float* x  = (const float*)d_in[0];
    const float* W1 = (const float*)d_in[1];
    const float* g1 = (const float*)d_in[2];
    const float* b1 = (const float*)d_in[3];
    const float* m1 = (const float*)d_in[4];
    const float* v1 = (const float*)d_in[5];
    const float* W2 = (const float*)d_in[6];
    const float* g2 = (const float*)d_in[7];
    const float* b2 = (const float*)d_in[8];
    const float* m2 = (const float*)d_in[9];
    const float* v2 = (const float*)d_in[10];
    const float* W5 = (const float*)d_in[11];
    const float* g5 = (const float*)d_in[12];
    const float* b5 = (const float*)d_in[13];
    const float* m5 = (const float*)d_in[14];
    const float* v5 = (const float*)d_in[15];
    const float* W6 = (const float*)d_in[16];
    const float* g6 = (const float*)d_in[17];
    const float* b6 = (const float*)d_in[18];
    const float* m6 = (const float*)d_in[19];
    const float* v6 = (const float*)d_in[20];
    const float* W9 = (const float*)d_in[21];
    float* out = (float*)d_out;

    cudaFuncSetAttribute(conv6_kernel, cudaFuncAttributeMaxDynamicSharedMemorySize, C6_SMEM);
    cudaFuncSetAttribute(knn2_part, cudaFuncAttributeMaxDynamicSharedMemorySize, KNN2_SMEM);

    prep_a<<<64, 256>>>(W6, g6, v6);
    prep_bc<<<16, 256>>>(W1, g1, b1, m1, v1, W2, g2, b2, m2, v2,
                         W5, g5, b5, m5, v5, g6, b6, m6, v6);

    knn1_part<<<dim3(32, SPLIT1, BATCH), 128>>>(x);   // 3rd

    dim3 g32(32, 4);
    layer1_kernel<<<g32, 128>>>(x);                   // 4th launch -> profiled

    knn2_part<<<dim3(32, SPLIT2, BATCH), 128, KNN2_SMEM>>>();

    merge2_kernel<<<64, 256>>>();

    layer2_kernel<<<BATCH*NPTS/2, 128>>>();

    conv5_kernel<<<dim3(NPTS/C5PTS, BATCH), 128>>>();

    conv6_kernel<<<256, 256, C6_SMEM>>>(W9, out);
}